// round 3
// baseline (speedup 1.0000x reference)
#include <cuda_runtime.h>
#include <cuda_fp16.h>

// Problem: B=2, C=4, D=64, H=256, W=256
#define Ww    256
#define HW    65536        // H*W
#define DHW   4194304      // D*H*W
#define DHW4  1048576      // DHW/4
#define NQ    2097152      // B*DHW/4  (threads, 4 voxels each)
#define NELEM 25165824.0   // B*(C-1)*DHW

// Scratch: softmax probs classes 1..3 as fp16, layout (B, 3, D, H, W). 50.3 MB.
__device__ __align__(16) __half g_probs[2 * 3 * DHW];
__device__ double   g_acc;
__device__ unsigned g_done = 0;

// ---------------- Pass 1: softmax (4 voxels/thread), write fp16, zero g_acc ---
__global__ void __launch_bounds__(256)
softmax_kernel(const float* __restrict__ logits) {
    int t = blockIdx.x * blockDim.x + threadIdx.x;
    if (t == 0) g_acc = 0.0;
    if (t >= NQ) return;
    int b  = t >> 20;
    int v4 = t & (DHW4 - 1);
    const float4* L = (const float4*)logits + (size_t)b * 4 * DHW4 + v4;
    float4 x0 = L[0 * DHW4];
    float4 x1 = L[1 * DHW4];
    float4 x2 = L[2 * DHW4];
    float4 x3 = L[3 * DHW4];
    float4 p1, p2, p3;
#define SM1(comp) {                                                       \
        float a = x0.comp, bb = x1.comp, c = x2.comp, dd = x3.comp;       \
        float m  = fmaxf(fmaxf(a, bb), fmaxf(c, dd));                     \
        float e0 = __expf(a - m), e1 = __expf(bb - m);                    \
        float e2 = __expf(c - m), e3 = __expf(dd - m);                    \
        float inv = __frcp_rn(e0 + e1 + e2 + e3);                        \
        p1.comp = e1 * inv; p2.comp = e2 * inv; p3.comp = e3 * inv; }
    SM1(x) SM1(y) SM1(z) SM1(w)
#undef SM1
    __half* base = g_probs + (size_t)b * 3 * DHW;
#define PACKST(c, p) {                                                    \
        __half2 lo = __floats2half2_rn(p.x, p.y);                         \
        __half2 hi = __floats2half2_rn(p.z, p.w);                         \
        uint2 u; u.x = *(unsigned*)&lo; u.y = *(unsigned*)&hi;            \
        *(uint2*)(base + (size_t)(c) * DHW + ((size_t)v4 << 2)) = u; }
    PACKST(0, p1) PACKST(1, p2) PACKST(2, p3)
#undef PACKST
}

__device__ __forceinline__ float4 ld_h4(const __half* p) {
    uint2 u = *(const uint2*)p;
    __half2 lo = *(__half2*)&u.x, hi = *(__half2*)&u.y;
    float2 a = __half22float2(lo), b = __half22float2(hi);
    return make_float4(a.x, a.y, b.x, b.y);
}
__device__ __forceinline__ float f4get(const float4& f, int j) {
    switch (j) { case 0: return f.x; case 1: return f.y; case 2: return f.z; default: return f.w; }
}
__device__ __forceinline__ int i4get(const int4& f, int j) {
    switch (j) { case 0: return f.x; case 1: return f.y; case 2: return f.z; default: return f.w; }
}

// ---------------- Pass 2: stencil + loss + grid reduction + finalize ----------
__global__ void __launch_bounds__(256)
loss_kernel(const int* __restrict__ targets, float* __restrict__ out) {
    int t = blockIdx.x * blockDim.x + threadIdx.x;
    float acc = 0.f;
    {
        int w4 = t & 63;
        int h  = (t >> 6) & 255;
        int d  = (t >> 14) & 63;
        int b  = t >> 20;
        int v  = d * HW + h * Ww + (w4 << 2);

        const __half* Pb = g_probs + (size_t)b * 3 * DHW;
        const int*    Tb = targets + (size_t)b * DHW;
        const float4 zf = make_float4(0.f, 0.f, 0.f, 0.f);
        const int4   zi = make_int4(0, 0, 0, 0);

        float4 Cn[3], Dm[3], Dp[3], Hm[3], Hp[3];
        float  Lw[3], Rw[3];
#pragma unroll
        for (int c = 0; c < 3; c++) {
            const __half* base = Pb + (size_t)c * DHW + v;
            Cn[c] = ld_h4(base);
            Dm[c] = (d > 0)   ? ld_h4(base - HW) : zf;
            Dp[c] = (d < 63)  ? ld_h4(base + HW) : zf;
            Hm[c] = (h > 0)   ? ld_h4(base - Ww) : zf;
            Hp[c] = (h < 255) ? ld_h4(base + Ww) : zf;
            Lw[c] = (w4 > 0)  ? __half2float(base[-1]) : 0.f;
            Rw[c] = (w4 < 63) ? __half2float(base[4])  : 0.f;
        }
        const int* tb = Tb + v;
        int4 tC  = *(const int4*)tb;
        int4 tDm = (d > 0)   ? *(const int4*)(tb - HW) : zi;
        int4 tDp = (d < 63)  ? *(const int4*)(tb + HW) : zi;
        int4 tHm = (h > 0)   ? *(const int4*)(tb - Ww) : zi;
        int4 tHp = (h < 255) ? *(const int4*)(tb + Ww) : zi;
        int  tL  = (w4 > 0)  ? tb[-1] : 0;
        int  tR  = (w4 < 63) ? tb[4]  : 0;

#pragma unroll
        for (int j = 0; j < 4; j++) {
            int tc  = i4get(tC, j);
            int tl  = (j == 0) ? tL : i4get(tC, j - 1);
            int tr  = (j == 3) ? tR : i4get(tC, j + 1);
            int td0 = i4get(tDm, j), td1 = i4get(tDp, j);
            int th0 = i4get(tHm, j), th1 = i4get(tHp, j);
#pragma unroll
            for (int c = 0; c < 3; c++) {
                float pl = (j == 0) ? Lw[c] : f4get(Cn[c], j - 1);
                float pr = (j == 3) ? Rw[c] : f4get(Cn[c], j + 1);
                float lap_p = f4get(Dm[c], j) + f4get(Dp[c], j)
                            + f4get(Hm[c], j) + f4get(Hp[c], j)
                            + pl + pr - 6.f * f4get(Cn[c], j);
                int c1  = c + 1;
                int cnt = (td0 == c1) + (td1 == c1) + (th0 == c1) + (th1 == c1)
                        + (tl == c1) + (tr == c1);
                float lap_t = (float)(cnt - 6 * (tc == c1));
                float diff = fabsf(lap_p) - fabsf(lap_t);
                acc = fmaf(diff, diff, acc);
            }
        }
    }
    // block reduction
#pragma unroll
    for (int o = 16; o; o >>= 1) acc += __shfl_down_sync(0xffffffffu, acc, o);
    __shared__ float ws[8];
    __shared__ unsigned ticket;
    int lane = threadIdx.x & 31, wid = threadIdx.x >> 5;
    if (lane == 0) ws[wid] = acc;
    __syncthreads();
    if (wid == 0) {
        acc = (lane < 8) ? ws[lane] : 0.f;
#pragma unroll
        for (int o = 4; o; o >>= 1) acc += __shfl_down_sync(0xffffffffu, acc, o);
        if (lane == 0) {
            atomicAdd(&g_acc, (double)acc);
            __threadfence();
            ticket = atomicAdd(&g_done, 1u);
        }
    }
    __syncthreads();
    if (threadIdx.x == 0 && ticket == gridDim.x - 1) {
        double total = atomicAdd(&g_acc, 0.0);   // coherent read via L2
        out[0] = (float)(total * (1.0 / NELEM));
        g_done = 0;
    }
}

extern "C" void kernel_launch(void* const* d_in, const int* in_sizes, int n_in,
                              void* d_out, int out_size) {
    const float* logits  = (const float*)d_in[0];
    const int*   targets = (const int*)d_in[1];
    float* out = (float*)d_out;

    softmax_kernel<<<NQ / 256, 256>>>(logits);
    loss_kernel<<<NQ / 256, 256>>>(targets, out);
}

// round 4
// speedup vs baseline: 1.2418x; 1.2418x over previous
#include <cuda_runtime.h>
#include <cuda_fp16.h>

// Problem: B=2, C=4, D=64, H=256, W=256
#define Ww    256
#define HW    65536        // H*W
#define DHW   4194304      // D*H*W
#define DHW4  1048576      // DHW/4
#define NQ    2097152      // B*DHW/4  (threads, 4 voxels each)
#define NELEM 25165824.0   // B*(C-1)*DHW

// Scratch: per-voxel packed probs {h2(p1,p2), h2(p3,0)}. (B,D,H,W) voxels. 67 MB.
__device__ __align__(16) uint2 g_probs[2 * DHW];
__device__ double   g_acc;
__device__ unsigned g_done = 0;

__device__ __forceinline__ unsigned h2u(__half2 h) { return *(unsigned*)&h; }
__device__ __forceinline__ __half2 u2h(unsigned u) { return *(__half2*)&u; }

// ---------------- Pass 1: softmax (4 voxels/thread), packed fp16 store --------
__global__ void __launch_bounds__(256)
softmax_kernel(const float* __restrict__ logits) {
    int t = blockIdx.x * blockDim.x + threadIdx.x;
    if (t == 0) g_acc = 0.0;
    if (t >= NQ) return;
    int b  = t >> 20;
    int v4 = t & (DHW4 - 1);
    const float4* L = (const float4*)logits + (size_t)b * 4 * DHW4 + v4;
    float4 x0 = L[0 * DHW4];
    float4 x1 = L[1 * DHW4];
    float4 x2 = L[2 * DHW4];
    float4 x3 = L[3 * DHW4];
    float4 p1, p2, p3;
#define SM1(comp) {                                                       \
        float a = x0.comp, bb = x1.comp, c = x2.comp, dd = x3.comp;       \
        float m  = fmaxf(fmaxf(a, bb), fmaxf(c, dd));                     \
        float e0 = __expf(a - m), e1 = __expf(bb - m);                    \
        float e2 = __expf(c - m), e3 = __expf(dd - m);                    \
        float inv = __frcp_rn(e0 + e1 + e2 + e3);                        \
        p1.comp = e1 * inv; p2.comp = e2 * inv; p3.comp = e3 * inv; }
    SM1(x) SM1(y) SM1(z) SM1(w)
#undef SM1
    uint4 s0, s1;
    s0.x = h2u(__floats2half2_rn(p1.x, p2.x)); s0.y = h2u(__floats2half2_rn(p3.x, 0.f));
    s0.z = h2u(__floats2half2_rn(p1.y, p2.y)); s0.w = h2u(__floats2half2_rn(p3.y, 0.f));
    s1.x = h2u(__floats2half2_rn(p1.z, p2.z)); s1.y = h2u(__floats2half2_rn(p3.z, 0.f));
    s1.z = h2u(__floats2half2_rn(p1.w, p2.w)); s1.w = h2u(__floats2half2_rn(p3.w, 0.f));
    uint4* dst = (uint4*)g_probs + ((size_t)b * (DHW / 2)) + ((size_t)v4 << 1);
    dst[0] = s0;
    dst[1] = s1;
}

// ---------------- Pass 2: stencil + loss + grid reduction + finalize ----------
__global__ void __launch_bounds__(256, 4)
loss_kernel(const int* __restrict__ targets, float* __restrict__ out) {
    int t = blockIdx.x * blockDim.x + threadIdx.x;
    int w4 = t & 63;
    int h  = (t >> 6) & 255;
    int d  = (t >> 14) & 63;
    int b  = t >> 20;
    size_t v = (size_t)d * HW + h * Ww + (w4 << 2);

    const uint2* base = g_probs + (size_t)b * DHW + v;
    const int*   tb   = targets + (size_t)b * DHW + v;

    const uint4 z4 = make_uint4(0, 0, 0, 0);
    const uint2 z2 = make_uint2(0, 0);
    const int4  zi = make_int4(0, 0, 0, 0);

    // ---- prob loads (all issued up front for MLP) ----
    uint4 c01 = *(const uint4*)base;
    uint4 c23 = *(const uint4*)(base + 2);
    uint2 lfu = (w4 > 0)  ? base[-1] : z2;
    uint2 rtu = (w4 < 63) ? base[4]  : z2;
    const uint4* pdm = (const uint4*)(base - HW);
    const uint4* pdp = (const uint4*)(base + HW);
    const uint4* phm = (const uint4*)(base - Ww);
    const uint4* php = (const uint4*)(base + Ww);
    uint4 dm0 = (d > 0)   ? pdm[0] : z4, dm1 = (d > 0)   ? pdm[1] : z4;
    uint4 dp0 = (d < 63)  ? pdp[0] : z4, dp1 = (d < 63)  ? pdp[1] : z4;
    uint4 hm0 = (h > 0)   ? phm[0] : z4, hm1 = (h > 0)   ? phm[1] : z4;
    uint4 hp0 = (h < 255) ? php[0] : z4, hp1 = (h < 255) ? php[1] : z4;

    // ---- target loads ----
    int4 tC  = *(const int4*)tb;
    int4 tDm = (d > 0)   ? *(const int4*)(tb - HW) : zi;
    int4 tDp = (d < 63)  ? *(const int4*)(tb + HW) : zi;
    int4 tHm = (h > 0)   ? *(const int4*)(tb - Ww) : zi;
    int4 tHp = (h < 255) ? *(const int4*)(tb + Ww) : zi;
    int  tL  = (w4 > 0)  ? tb[-1] : 0;
    int  tR  = (w4 < 63) ? tb[4]  : 0;

    // ---- half2 stencil sums: A = classes(1,2), B = class 3 ----
    __half2 cA[4], cB[4];
    cA[0] = u2h(c01.x); cB[0] = u2h(c01.y);
    cA[1] = u2h(c01.z); cB[1] = u2h(c01.w);
    cA[2] = u2h(c23.x); cB[2] = u2h(c23.y);
    cA[3] = u2h(c23.z); cB[3] = u2h(c23.w);

    __half2 sA[4], sB[4];
    sA[0] = __hadd2(u2h(lfu.x), cA[1]); sB[0] = __hadd2(u2h(lfu.y), cB[1]);
    sA[1] = __hadd2(cA[0], cA[2]);      sB[1] = __hadd2(cB[0], cB[2]);
    sA[2] = __hadd2(cA[1], cA[3]);      sB[2] = __hadd2(cB[1], cB[3]);
    sA[3] = __hadd2(cA[2], u2h(rtu.x)); sB[3] = __hadd2(cB[2], u2h(rtu.y));

#define ACCROW(r0, r1)                                                     \
    sA[0] = __hadd2(sA[0], u2h(r0.x)); sB[0] = __hadd2(sB[0], u2h(r0.y)); \
    sA[1] = __hadd2(sA[1], u2h(r0.z)); sB[1] = __hadd2(sB[1], u2h(r0.w)); \
    sA[2] = __hadd2(sA[2], u2h(r1.x)); sB[2] = __hadd2(sB[2], u2h(r1.y)); \
    sA[3] = __hadd2(sA[3], u2h(r1.z)); sB[3] = __hadd2(sB[3], u2h(r1.w));
    ACCROW(dm0, dm1)
    ACCROW(dp0, dp1)
    ACCROW(hm0, hm1)
    ACCROW(hp0, hp1)
#undef ACCROW

    const __half2 m6 = __floats2half2_rn(-6.f, -6.f);
#pragma unroll
    for (int j = 0; j < 4; ++j) {
        sA[j] = __hfma2(cA[j], m6, sA[j]);
        sB[j] = __hfma2(cB[j], m6, sB[j]);
    }

    // ---- byte-packed target neighbor counts ----
#define ENC(x) (1u << ((unsigned)(x) << 3))
    unsigned eC0 = ENC(tC.x), eC1 = ENC(tC.y), eC2 = ENC(tC.z), eC3 = ENC(tC.w);
    unsigned eL = ENC(tL), eR = ENC(tR);
    unsigned ns[4];
    ns[0] = ENC(tDm.x) + ENC(tDp.x) + ENC(tHm.x) + ENC(tHp.x) + eL  + eC1;
    ns[1] = ENC(tDm.y) + ENC(tDp.y) + ENC(tHm.y) + ENC(tHp.y) + eC0 + eC2;
    ns[2] = ENC(tDm.z) + ENC(tDp.z) + ENC(tHm.z) + ENC(tHp.z) + eC1 + eC3;
    ns[3] = ENC(tDm.w) + ENC(tDp.w) + ENC(tHm.w) + ENC(tHp.w) + eC2 + eR;
    // note: invalid taps were zeroed ints -> ENC()=1 pollutes byte 0 only (unused)
    unsigned ec[4] = {eC0, eC1, eC2, eC3};
#undef ENC

    float acc = 0.f;
#pragma unroll
    for (int j = 0; j < 4; ++j) {
        float2 f12 = __half22float2(sA[j]);
        float  f3  = __half2float(__low2half(sB[j]));
        float lp[3] = {f12.x, f12.y, f3};
        unsigned n = ns[j], e = ec[j];
#pragma unroll
        for (int c1 = 1; c1 <= 3; ++c1) {
            int cnt = (int)((n >> (c1 * 8)) & 0xFFu);
            int isc = (int)((e >> (c1 * 8)) & 1u);
            float lt = (float)(cnt - 6 * isc);
            float diff = fabsf(lp[c1 - 1]) - fabsf(lt);
            acc = fmaf(diff, diff, acc);
        }
    }

    // ---- block reduction -> double atomic -> last-block finalize ----
#pragma unroll
    for (int o = 16; o; o >>= 1) acc += __shfl_down_sync(0xffffffffu, acc, o);
    __shared__ float ws[8];
    __shared__ unsigned ticket;
    int lane = threadIdx.x & 31, wid = threadIdx.x >> 5;
    if (lane == 0) ws[wid] = acc;
    __syncthreads();
    if (wid == 0) {
        acc = (lane < 8) ? ws[lane] : 0.f;
#pragma unroll
        for (int o = 4; o; o >>= 1) acc += __shfl_down_sync(0xffffffffu, acc, o);
        if (lane == 0) {
            atomicAdd(&g_acc, (double)acc);
            __threadfence();
            ticket = atomicAdd(&g_done, 1u);
        }
    }
    __syncthreads();
    if (threadIdx.x == 0 && ticket == gridDim.x - 1) {
        double total = atomicAdd(&g_acc, 0.0);
        out[0] = (float)(total * (1.0 / NELEM));
        g_done = 0;
    }
}

extern "C" void kernel_launch(void* const* d_in, const int* in_sizes, int n_in,
                              void* d_out, int out_size) {
    const float* logits  = (const float*)d_in[0];
    const int*   targets = (const int*)d_in[1];
    float* out = (float*)d_out;

    softmax_kernel<<<NQ / 256, 256>>>(logits);
    loss_kernel<<<NQ / 256, 256>>>(targets, out);
}